// round 16
// baseline (speedup 1.0000x reference)
#include <cuda_runtime.h>
#include <cuda_bf16.h>
#include <cstdint>

#define F 26
#define D 128
#define NROWS 100000
#define B 4096
#define T (B * 20)

// ---- per-warp gather pipeline ---------------------------------------------
// Lane l owns the l-th float4 (16B) of each 512B row. Rows go global->shared
// via cp.async, stages of 3 rows, double buffered (6 slots = 3KB per warp).
// Ring shrunk 8->6 slots so the block fits 28KB smem -> 8 blocks/SM (100%
// theoretical occupancy at 256 threads).
__device__ __forceinline__ float4 gather_accum(
    const int* __restrict__ vals, int lo, int hi,
    const char* __restrict__ tabb, uint32_t sb0,
    int lane, const float4* __restrict__ bufw)
{
    float4 a0 = make_float4(0.f, 0.f, 0.f, 0.f);
    float4 a1 = make_float4(0.f, 0.f, 0.f, 0.f);

    for (int base = lo; base < hi; base += 32) {
        const int n = min(32, hi - base);
        int myidx = 0;
        if (base + lane < hi) myidx = __ldg(vals + base + lane);

        const int nstage = (n + 2) / 3;
        int sbuf = 0;
        int prevcnt = 0;

        for (int st = 0; st < nstage; ++st) {
            const int cnt = min(3, n - st * 3);
            #pragma unroll
            for (int q = 0; q < 3; ++q) {
                if (q < cnt) {
                    int r = __shfl_sync(0xffffffffu, myidx, st * 3 + q);
                    const char* src = tabb + ((size_t)(unsigned)r << 9) + (lane << 4);
                    uint32_t dst = sb0 + (uint32_t)((sbuf * 3 + q) << 9);
                    asm volatile("cp.async.cg.shared.global [%0], [%1], 16;\n"
                                 :: "r"(dst), "l"(src));
                }
            }
            asm volatile("cp.async.commit_group;\n");

            if (st > 0) {
                asm volatile("cp.async.wait_group 1;\n");
                const int pb = (sbuf ^ 1) * 3;
                #pragma unroll
                for (int q = 0; q < 3; ++q) {
                    if (q < prevcnt) {
                        float4 v = bufw[(pb + q) * 32 + lane];
                        if (q & 1) { a1.x += v.x; a1.y += v.y; a1.z += v.z; a1.w += v.w; }
                        else       { a0.x += v.x; a0.y += v.y; a0.z += v.z; a0.w += v.w; }
                    }
                }
            }
            prevcnt = cnt;
            sbuf ^= 1;
        }

        if (nstage > 0) {
            asm volatile("cp.async.wait_group 0;\n");
            const int pb = (sbuf ^ 1) * 3;
            #pragma unroll
            for (int q = 0; q < 3; ++q) {
                if (q < prevcnt) {
                    float4 v = bufw[(pb + q) * 32 + lane];
                    if (q & 1) { a1.x += v.x; a1.y += v.y; a1.z += v.z; a1.w += v.w; }
                    else       { a0.x += v.x; a0.y += v.y; a0.z += v.z; a0.w += v.w; }
                }
            }
        }
    }

    float4 acc;
    acc.x = a0.x + a1.x; acc.y = a0.y + a1.y;
    acc.z = a0.z + a1.z; acc.w = a0.w + a1.w;
    return acc;
}

// ---- fused, sum-split kernel ----------------------------------------------
// Block = 8 warps = 8 consecutive bags of one feature. Offsets are cumulative,
// so the 8 bags occupy ONE contiguous range of vals, split EVENLY over the 8
// warps (crossing bag boundaries) -> zero intra-block imbalance.
// Per-bag partials combine via smem atomicAdd in component-major layout
// part[j][c][lane] (bank==lane -> conflict-free).
__global__ __launch_bounds__(256, 8) void ebag_fused(
    const float* __restrict__ tables,   // [F, NROWS, D]
    const int* __restrict__ values,     // [F, T]
    const int* __restrict__ offsets,    // [F, B+1]
    float* __restrict__ out)            // [B, F, D]
{
    __shared__ float4 buf[8][6][32];            // 24KB: per-warp pipeline rings
    __shared__ float part[8][4][32];            // 4KB: per-bag partials, comp-major

    const int lane = threadIdx.x & 31;
    const int warp = threadIdx.x >> 5;
    const int f    = blockIdx.y;
    const int bag0 = blockIdx.x * 8;

    const int* offs = offsets + f * (B + 1);
    // 9 boundary offsets held warp-wide in one register, fetched via shfl.
    int off_l = 0;
    if (lane < 9) off_l = __ldg(offs + bag0 + lane);

    // zero the partial buffer (256 threads x 4 floats = 1024 floats)
    reinterpret_cast<float4*>(&part[0][0][0])[threadIdx.x] =
        make_float4(0.f, 0.f, 0.f, 0.f);
    __syncthreads();

    const int S = __shfl_sync(0xffffffffu, off_l, 0);
    const int E = __shfl_sync(0xffffffffu, off_l, 8);
    const int total = E - S;

    const int* vals = values + (size_t)f * T;
    const char* tabb = reinterpret_cast<const char*>(
        tables + (size_t)f * NROWS * D);
    uint32_t sb0 = (uint32_t)__cvta_generic_to_shared(&buf[warp][0][lane]);

    // this warp's even share of the concatenated range
    int lo = S + (int)(((long long)total * warp) >> 3);
    int hi = S + (int)(((long long)total * (warp + 1)) >> 3);

    if (lo < hi) {
        // find first bag j containing lo: largest j with offs[j] <= lo
        int j = 0;
        int oj1 = __shfl_sync(0xffffffffu, off_l, 1);
        while (j < 7) {
            if (oj1 > lo) break;
            ++j;
            oj1 = __shfl_sync(0xffffffffu, off_l, j + 1);
        }

        int p = lo;
        while (p < hi) {
            const int ce = min(hi, oj1);        // chunk end within bag j
            if (ce > p) {
                float4 acc = gather_accum(vals, p, ce, tabb, sb0, lane,
                                          &buf[warp][0][0]);
                // conflict-free: bank == lane for every component
                atomicAdd(&part[j][0][lane], acc.x);
                atomicAdd(&part[j][1][lane], acc.y);
                atomicAdd(&part[j][2][lane], acc.z);
                atomicAdd(&part[j][3][lane], acc.w);
                p = ce;
            }
            if (p >= hi) break;
            ++j;
            oj1 = __shfl_sync(0xffffffffu, off_l, j + 1);
        }
    }
    __syncthreads();

    // warp w writes bag w (always: empty bags must be 0, d_out is poisoned)
    float4 res;
    res.x = part[warp][0][lane];
    res.y = part[warp][1][lane];
    res.z = part[warp][2][lane];
    res.w = part[warp][3][lane];
    float4* o = reinterpret_cast<float4*>(out) + ((size_t)(bag0 + warp) * F + f) * 32;
    o[lane] = res;
}

extern "C" void kernel_launch(void* const* d_in, const int* in_sizes, int n_in,
                              void* d_out, int out_size) {
    const float* tables  = (const float*)d_in[0];
    const int*   values  = (const int*)d_in[1];
    const int*   offsets = (const int*)d_in[2];
    float* out = (float*)d_out;

    dim3 grid(B / 8, F);   // feature on y: blocks of one feature grouped -> L2 reuse
    dim3 block(256);       // 8 warps, 8 bags, sum-split evenly
    ebag_fused<<<grid, block>>>(tables, values, offsets, out);
}

// round 17
// speedup vs baseline: 1.0275x; 1.0275x over previous
#include <cuda_runtime.h>
#include <cuda_bf16.h>
#include <cstdint>

#define F 26
#define D 128
#define NROWS 100000
#define B 4096
#define T (B * 20)

// ---- per-warp gather pipeline ---------------------------------------------
// Lane l owns the l-th float4 (16B) of each 512B row. Rows go global->shared
// via cp.async, stages of 4 rows, double buffered (8 slots = 4KB per warp).
// Stage indices are fetched with UNIFORM scalar __ldg (all lanes same addr,
// 1 wavefront, L1-cached): no SHFL broadcasts, no 32-chunk staging loop.
__device__ __forceinline__ float4 gather_accum(
    const int* __restrict__ vals, int lo, int hi,
    const char* __restrict__ tabb, uint32_t sb0,
    int lane, const float4* __restrict__ bufw)
{
    float4 a0 = make_float4(0.f, 0.f, 0.f, 0.f);
    float4 a1 = make_float4(0.f, 0.f, 0.f, 0.f);

    const int n = hi - lo;
    const int nstage = (n + 3) >> 2;
    int sbuf = 0;
    int prevcnt = 0;

    for (int st = 0; st < nstage; ++st) {
        const int base = lo + (st << 2);
        const int cnt = min(4, hi - base);

        // uniform index fetch: every lane loads the same scalar (L1 hit-heavy)
        int r0 = __ldg(vals + base);
        int r1 = (cnt > 1) ? __ldg(vals + base + 1) : 0;
        int r2 = (cnt > 2) ? __ldg(vals + base + 2) : 0;
        int r3 = (cnt > 3) ? __ldg(vals + base + 3) : 0;

        const int rr0 = r0, rr1 = r1, rr2 = r2, rr3 = r3;
        const int rr[4] = {rr0, rr1, rr2, rr3};
        #pragma unroll
        for (int q = 0; q < 4; ++q) {
            if (q < cnt) {
                const char* src = tabb + ((size_t)(unsigned)rr[q] << 9) + (lane << 4);
                uint32_t dst = sb0 + (uint32_t)((sbuf * 4 + q) << 9);
                asm volatile("cp.async.cg.shared.global [%0], [%1], 16;\n"
                             :: "r"(dst), "l"(src));
            }
        }
        asm volatile("cp.async.commit_group;\n");

        // consume the previous stage while this one is in flight
        if (st > 0) {
            asm volatile("cp.async.wait_group 1;\n");
            const int pb = (sbuf ^ 1) * 4;
            #pragma unroll
            for (int q = 0; q < 4; ++q) {
                if (q < prevcnt) {
                    float4 v = bufw[(pb + q) * 32 + lane];
                    if (q & 1) { a1.x += v.x; a1.y += v.y; a1.z += v.z; a1.w += v.w; }
                    else       { a0.x += v.x; a0.y += v.y; a0.z += v.z; a0.w += v.w; }
                }
            }
        }
        prevcnt = cnt;
        sbuf ^= 1;
    }

    // drain the last stage
    if (nstage > 0) {
        asm volatile("cp.async.wait_group 0;\n");
        const int pb = (sbuf ^ 1) * 4;
        #pragma unroll
        for (int q = 0; q < 4; ++q) {
            if (q < prevcnt) {
                float4 v = bufw[(pb + q) * 32 + lane];
                if (q & 1) { a1.x += v.x; a1.y += v.y; a1.z += v.z; a1.w += v.w; }
                else       { a0.x += v.x; a0.y += v.y; a0.z += v.z; a0.w += v.w; }
            }
        }
    }

    float4 acc;
    acc.x = a0.x + a1.x; acc.y = a0.y + a1.y;
    acc.z = a0.z + a1.z; acc.w = a0.w + a1.w;
    return acc;
}

// ---- fused, sum-split kernel ----------------------------------------------
// Block = 8 warps = 8 consecutive bags of one feature. Offsets are cumulative,
// so the 8 bags occupy ONE contiguous range of vals, split EVENLY over the 8
// warps (crossing bag boundaries) -> zero intra-block imbalance.
// Per-bag partials combine via smem atomicAdd in component-major layout
// part[j][c][lane] (bank==lane -> conflict-free).
__global__ __launch_bounds__(256, 6) void ebag_fused(
    const float* __restrict__ tables,   // [F, NROWS, D]
    const int* __restrict__ values,     // [F, T]
    const int* __restrict__ offsets,    // [F, B+1]
    float* __restrict__ out)            // [B, F, D]
{
    __shared__ float4 buf[8][8][32];            // 32KB: per-warp pipeline rings
    __shared__ float part[8][4][32];            // 4KB: per-bag partials, comp-major

    const int lane = threadIdx.x & 31;
    const int warp = threadIdx.x >> 5;
    const int f    = blockIdx.y;
    const int bag0 = blockIdx.x * 8;

    const int* offs = offsets + f * (B + 1);
    // 9 boundary offsets held warp-wide in one register, fetched via shfl.
    int off_l = 0;
    if (lane < 9) off_l = __ldg(offs + bag0 + lane);

    // zero the partial buffer (256 threads x 4 floats = 1024 floats)
    reinterpret_cast<float4*>(&part[0][0][0])[threadIdx.x] =
        make_float4(0.f, 0.f, 0.f, 0.f);
    __syncthreads();

    const int S = __shfl_sync(0xffffffffu, off_l, 0);
    const int E = __shfl_sync(0xffffffffu, off_l, 8);
    const int total = E - S;

    const int* vals = values + (size_t)f * T;
    const char* tabb = reinterpret_cast<const char*>(
        tables + (size_t)f * NROWS * D);
    uint32_t sb0 = (uint32_t)__cvta_generic_to_shared(&buf[warp][0][lane]);

    // this warp's even share of the concatenated range
    int lo = S + (int)(((long long)total * warp) >> 3);
    int hi = S + (int)(((long long)total * (warp + 1)) >> 3);

    if (lo < hi) {
        // find first bag j containing lo: largest j with offs[j] <= lo
        int j = 0;
        int oj1 = __shfl_sync(0xffffffffu, off_l, 1);
        while (j < 7) {
            if (oj1 > lo) break;
            ++j;
            oj1 = __shfl_sync(0xffffffffu, off_l, j + 1);
        }

        int p = lo;
        while (p < hi) {
            const int ce = min(hi, oj1);        // chunk end within bag j
            if (ce > p) {
                float4 acc = gather_accum(vals, p, ce, tabb, sb0, lane,
                                          &buf[warp][0][0]);
                // conflict-free: bank == lane for every component
                atomicAdd(&part[j][0][lane], acc.x);
                atomicAdd(&part[j][1][lane], acc.y);
                atomicAdd(&part[j][2][lane], acc.z);
                atomicAdd(&part[j][3][lane], acc.w);
                p = ce;
            }
            if (p >= hi) break;
            ++j;
            oj1 = __shfl_sync(0xffffffffu, off_l, j + 1);
        }
    }
    __syncthreads();

    // warp w writes bag w (always: empty bags must be 0, d_out is poisoned)
    float4 res;
    res.x = part[warp][0][lane];
    res.y = part[warp][1][lane];
    res.z = part[warp][2][lane];
    res.w = part[warp][3][lane];
    float4* o = reinterpret_cast<float4*>(out) + ((size_t)(bag0 + warp) * F + f) * 32;
    o[lane] = res;
}

extern "C" void kernel_launch(void* const* d_in, const int* in_sizes, int n_in,
                              void* d_out, int out_size) {
    const float* tables  = (const float*)d_in[0];
    const int*   values  = (const int*)d_in[1];
    const int*   offsets = (const int*)d_in[2];
    float* out = (float*)d_out;

    dim3 grid(B / 8, F);   // feature on y: blocks of one feature grouped -> L2 reuse
    dim3 block(256);       // 8 warps, 8 bags, sum-split evenly
    ebag_fused<<<grid, block>>>(tables, values, offsets, out);
}